// round 15
// baseline (speedup 1.0000x reference)
#include <cuda_runtime.h>

#define TT 256

// ---------------------------------------------------------------------------
// Workspace regions (zero-initialized device global; halos stay zero forever).
//  P0p [4,1,36,36,256]    P2p [4,16,18,18,256]   P4p [4,32,10,10,256]
//  P5  [4,64,8,8,256]     P6p [4,64,18,18,256]   P7 [4,32,16,16,256]
// ---------------------------------------------------------------------------
#define O_P0 0L
#define O_P2 1327104L
#define O_P4 6635520L
#define O_P5 9912320L
#define O_P6 14106624L
#define O_P7 35340288L
#define WS_TOTAL 43728896L
__device__ float g_ws[WS_TOTAL];

__device__ __forceinline__ void ffma2(unsigned long long& acc,
                                      unsigned long long w,
                                      unsigned long long v) {
    asm("fma.rn.f32x2 %0, %1, %2, %0;" : "+l"(acc) : "l"(w), "l"(v));
}

#define DSR  0.9048374180359595f   // exp(-1/10)
#define PSC  0.27182818284590452f  // e/10
#define DREF 0.36787944117144233f  // exp(-1)

// ---------------------------------------------------------------------------
// Standalone dynamics kernel. MODE 0: psp only ; MODE 3: up2+spike+psp.
// ---------------------------------------------------------------------------
template<int MODE, int H, int W, int OPAD>
__global__ void dyn_kernel(const float* __restrict__ in, float* __restrict__ out,
                           int N)
{
    int n = blockIdx.x * blockDim.x + threadIdx.x;
    if (n >= N) return;

    constexpr int S  = (MODE == 3) ? 4 : 1;
    constexpr int CH = (S == 4) ? 8 : 16;
    constexpr int F4 = CH / 4;
    constexpr int NC = TT / CH;
    constexpr int Ho = H + 2 * OPAD;
    constexpr int Wo = W + 2 * OPAD;

    int x = n % W, y = (n / W) % H, bc = n / (W * H);

    const float* p[S];
    float w00 = 0.f, w01 = 0.f, w10 = 0.f, w11 = 0.f;

    if (MODE == 3) {
        constexpr int Hin = H / 2, Win = W / 2;
        int jy = y >> 1, jx = x >> 1;
        int ya, yb, xa, xb; float wya, wyb, wxa, wxb;
        if ((y & 1) == 0) { ya = (jy > 0) ? jy - 1 : 0; yb = jy; wya = 0.25f; wyb = 0.75f; }
        else              { ya = jy; yb = (jy + 1 < Hin) ? jy + 1 : Hin - 1; wya = 0.75f; wyb = 0.25f; }
        if ((x & 1) == 0) { xa = (jx > 0) ? jx - 1 : 0; xb = jx; wxa = 0.25f; wxb = 0.75f; }
        else              { xa = jx; xb = (jx + 1 < Win) ? jx + 1 : Win - 1; wxa = 0.75f; wxb = 0.25f; }
        const float* base = in + (long)bc * Hin * Win * TT;
        p[0] = base + ((long)ya * Win + xa) * TT; w00 = wya * wxa;
        p[1] = base + ((long)ya * Win + xb) * TT; w01 = wya * wxb;
        p[2] = base + ((long)yb * Win + xa) * TT; w10 = wyb * wxa;
        p[3] = base + ((long)yb * Win + xb) * TT; w11 = wyb * wxb;
    } else {
        p[0] = in + (long)n * TT;
    }

    float* ob = out + (((long)bc * Ho + (y + OPAD)) * Wo + (x + OPAD)) * TT;

    float g1 = 0.f, g2 = 0.f, r = 0.f;
    float4 A[S][F4], B[S][F4];

    auto load = [&](float4 (&buf)[S][F4], int c) {
        #pragma unroll
        for (int s = 0; s < S; s++)
            #pragma unroll
            for (int f = 0; f < F4; f++)
                buf[s][f] = *(const float4*)(p[s] + c * CH + f * 4);
    };

    auto compute = [&](float4 (&buf)[S][F4], int c) {
        #pragma unroll
        for (int f = 0; f < F4; f++) {
            float u[4];
            if (MODE == 3) {
                float4 a = buf[0][f], b = buf[1][f], cc = buf[2][f], d = buf[3][f];
                u[0] = w00 * a.x + w01 * b.x + w10 * cc.x + w11 * d.x;
                u[1] = w00 * a.y + w01 * b.y + w10 * cc.y + w11 * d.y;
                u[2] = w00 * a.z + w01 * b.z + w10 * cc.z + w11 * d.z;
                u[3] = w00 * a.w + w01 * b.w + w10 * cc.w + w11 * d.w;
            } else {
                float4 a = buf[0][f];
                u[0] = a.x; u[1] = a.y; u[2] = a.z; u[3] = a.w;
            }
            float o[4];
            #pragma unroll
            for (int j = 0; j < 4; j++) {
                if (MODE == 0) {
                    g1 = fmaf(DSR, g1, u[j]);
                    g2 = fmaf(DSR, g2, g1);
                    o[j] = PSC * (g2 - g1);
                } else {
                    float v = u[j] + r - 10.0f;
                    float s = (v >= 0.f) ? 1.f : 0.f;
                    r = DREF * (r - 20.f * s);
                    g1 = fmaf(DSR, g1, s);
                    g2 = fmaf(DSR, g2, g1);
                    o[j] = PSC * (g2 - g1);
                }
            }
            *(float4*)(ob + c * CH + f * 4) = make_float4(o[0], o[1], o[2], o[3]);
        }
    };

    load(A, 0);
    for (int c = 0; c < NC; c += 2) {
        load(B, c + 1);
        compute(A, c);
        if (c + 2 < NC) load(A, c + 2);
        compute(B, c + 1);
    }
}

// ---------------------------------------------------------------------------
// Fused conv + spike/psp epilogue. TW=2: 128-thread block, each thread owns 2
// timesteps (u64), PX x-adjacent pixels, OCG channels. Per (kh,ic):
// NCOL LDG.64 + KS*OCG/2 LDS.128 + KS*PX*OCG fma.rn.f32x2 (~80% FFMA2 share)
// with only PX*OCG u64 accumulator registers. Zero-padded input, guard-free.
// ---------------------------------------------------------------------------
template<int IC, int KS, int OCG, int PX, int EPI, int H, int W, int OC>
__global__ __launch_bounds__(128)
void conv_kernel(const float* __restrict__ in, const float* __restrict__ wgt,
                 float* __restrict__ out)
{
    constexpr int PAD  = KS / 2;
    constexpr int Hp   = H + 2 * PAD;
    constexpr int Wp   = W + 2 * PAD;
    constexpr int NCOL = KS + PX - 1;
    constexpr int WP   = W / PX;
    constexpr int SW_BYTES = IC * KS * KS * OCG * 8;
    constexpr int SA_BYTES = PX * OCG * 260 * 4;
    constexpr int SM_BYTES = SW_BYTES > SA_BYTES ? SW_BYTES : SA_BYTES;
    __shared__ __align__(16) unsigned char smem_raw[SM_BYTES];
    unsigned long long* sw = (unsigned long long*)smem_raw;
    float* sa = (float*)smem_raw;

    int tid = threadIdx.x;
    int t   = tid * 2;

    int pp = blockIdx.x;
    int x0 = (pp % WP) * PX;
    int y  = (pp / WP) % H;
    int b  = pp / (WP * H);
    int oc0 = blockIdx.y * OCG;

    for (int i = tid; i < IC * KS * KS * OCG; i += 128) {
        int o  = i % OCG;
        int rs = i / OCG;
        int ic = rs % IC;
        int kd = rs / IC;
        int kh = kd / KS, dx = kd % KS;
        unsigned u = __float_as_uint(
            wgt[((long)(oc0 + o) * IC + ic) * (KS * KS) + kh * KS + dx]);
        sw[i] = ((unsigned long long)u << 32) | u;
    }
    __syncthreads();

    unsigned long long acc[PX][OCG];
    #pragma unroll
    for (int p = 0; p < PX; p++)
        #pragma unroll
        for (int o = 0; o < OCG; o++) acc[p][o] = 0ull;

    constexpr long planeTp = (long)Hp * Wp * TT;
    const float* inb = in + ((long)b * IC * Hp + y) * (long)Wp * TT + (long)x0 * TT + t;

    #pragma unroll
    for (int kh = 0; kh < KS; kh++) {
        const float* rp = inb + (long)kh * Wp * TT;
        #pragma unroll 2
        for (int ic = 0; ic < IC; ic++) {
            const float* icb = rp + (long)ic * planeTp;
            unsigned long long v[NCOL];
            #pragma unroll
            for (int j = 0; j < NCOL; j++)
                v[j] = *(const unsigned long long*)(icb + j * TT);
            const unsigned long long* swp0 = sw + ((long)kh * KS * IC + ic) * OCG;
            #pragma unroll
            for (int dx = 0; dx < KS; dx++) {
                const unsigned long long* swp = swp0 + (long)dx * IC * OCG;
                if constexpr (OCG % 2 == 0) {
                    #pragma unroll
                    for (int o = 0; o < OCG; o += 2) {
                        ulonglong2 wv = *(const ulonglong2*)(swp + o);
                        #pragma unroll
                        for (int p = 0; p < PX; p++) {
                            ffma2(acc[p][o    ], wv.x, v[dx + p]);
                            ffma2(acc[p][o + 1], wv.y, v[dx + p]);
                        }
                    }
                } else {
                    #pragma unroll
                    for (int o = 0; o < OCG; o++) {
                        unsigned long long wv = swp[o];
                        #pragma unroll
                        for (int p = 0; p < PX; p++)
                            ffma2(acc[p][o], wv, v[dx + p]);
                    }
                }
            }
        }
    }

    __syncthreads();
    #pragma unroll
    for (int p = 0; p < PX; p++)
        #pragma unroll
        for (int o = 0; o < OCG; o++)
            *(unsigned long long*)(sa + (p * OCG + o) * 260 + t) = acc[p][o];
    __syncthreads();

    if (tid < PX * OCG) {
        float* row = sa + tid * 260;
        float g1 = 0.f, g2 = 0.f, r = 0.f;
        float4 nxt = *(float4*)row;
        for (int tt = 0; tt < TT; tt += 4) {
            float4 a = nxt;
            if (tt + 4 < TT) nxt = *(float4*)(row + tt + 4);
            float u[4] = {a.x, a.y, a.z, a.w};
            float o4[4];
            #pragma unroll
            for (int j = 0; j < 4; j++) {
                float v = u[j] + r - 10.0f;
                float s = (v >= 0.f) ? 1.f : 0.f;
                r = DREF * (r - 20.f * s);
                if (EPI == 4) {
                    o4[j] = s;
                } else {
                    g1 = fmaf(DSR, g1, s);
                    g2 = fmaf(DSR, g2, g1);
                    o4[j] = PSC * (g2 - g1);
                }
            }
            *(float4*)(row + tt) = make_float4(o4[0], o4[1], o4[2], o4[3]);
        }
    }
    __syncthreads();

    constexpr long planeT = (long)H * W * TT;
    #pragma unroll
    for (int p = 0; p < PX; p++) {
        float* ob = out + ((long)b * OC + oc0) * planeT + ((long)y * W + x0 + p) * TT + t;
        #pragma unroll
        for (int o = 0; o < OCG; o++)
            *(float2*)(ob + o * planeT) = *(const float2*)(sa + (p * OCG + o) * 260 + t);
    }
}

// ---------------------------------------------------------------------------
// Conv + FUSED POOL epilogue (pool/psp commutation). Unchanged from R13.
// ---------------------------------------------------------------------------
template<int IC, int KS, int OCG, int H, int W, int OC, int OP>
__global__ __launch_bounds__(64)
void convpool_kernel(const float* __restrict__ in, const float* __restrict__ wgt,
                     float* __restrict__ out)
{
    constexpr int PAD  = KS / 2;
    constexpr int Hp   = H + 2 * PAD;
    constexpr int Wp   = W + 2 * PAD;
    constexpr int NCOL = KS + 1;
    constexpr int NROW = KS + 1;
    constexpr int H2   = H / 2, W2 = W / 2;
    constexpr int Ho   = H2 + 2 * OP, Wo = W2 + 2 * OP;
    constexpr int SW_BYTES = IC * KS * KS * OCG * 8;
    constexpr int SA_BYTES = 4 * OCG * 260 * 4;
    constexpr int SM_BYTES = SW_BYTES > SA_BYTES ? SW_BYTES : SA_BYTES;
    __shared__ __align__(16) unsigned char smem_raw[SM_BYTES];
    unsigned long long* sw = (unsigned long long*)smem_raw;
    float* sa = (float*)smem_raw;

    int tid = threadIdx.x;
    int t   = tid * 4;

    int pp = blockIdx.x;
    int tx = pp % W2;
    int ty = (pp / W2) % H2;
    int b  = pp / (W2 * H2);
    int x0 = tx * 2, y0 = ty * 2;
    int oc0 = blockIdx.y * OCG;

    for (int i = tid; i < IC * KS * KS * OCG; i += 64) {
        int o  = i % OCG;
        int rs = i / OCG;
        int ic = rs % IC;
        int kd = rs / IC;
        int kh = kd / KS, dx = kd % KS;
        unsigned u = __float_as_uint(
            wgt[((long)(oc0 + o) * IC + ic) * (KS * KS) + kh * KS + dx]);
        sw[i] = ((unsigned long long)u << 32) | u;
    }
    __syncthreads();

    unsigned long long acc[2][2][OCG][2];
    #pragma unroll
    for (int py = 0; py < 2; py++)
        #pragma unroll
        for (int px = 0; px < 2; px++)
            #pragma unroll
            for (int o = 0; o < OCG; o++) { acc[py][px][o][0] = 0ull; acc[py][px][o][1] = 0ull; }

    constexpr long planeTp = (long)Hp * Wp * TT;
    const float* inb = in + ((long)b * IC * Hp + y0) * (long)Wp * TT + (long)x0 * TT + t;

    #pragma unroll
    for (int rr = 0; rr < NROW; rr++) {
        const float* rp = inb + (long)rr * Wp * TT;
        #pragma unroll 2
        for (int ic = 0; ic < IC; ic++) {
            const float* icb = rp + (long)ic * planeTp;
            ulonglong2 v[NCOL];
            #pragma unroll
            for (int j = 0; j < NCOL; j++)
                v[j] = *(const ulonglong2*)(icb + j * TT);
            #pragma unroll
            for (int py = 0; py < 2; py++) {
                int kh = rr - py;
                if (kh < 0 || kh >= KS) continue;
                const unsigned long long* swp0 = sw + ((long)kh * KS * IC + ic) * OCG;
                #pragma unroll
                for (int dx = 0; dx < KS; dx++) {
                    const unsigned long long* swp = swp0 + (long)dx * IC * OCG;
                    if constexpr (OCG % 2 == 0) {
                        #pragma unroll
                        for (int o = 0; o < OCG; o += 2) {
                            ulonglong2 wv = *(const ulonglong2*)(swp + o);
                            #pragma unroll
                            for (int px = 0; px < 2; px++) {
                                ffma2(acc[py][px][o    ][0], wv.x, v[dx + px].x);
                                ffma2(acc[py][px][o    ][1], wv.x, v[dx + px].y);
                                ffma2(acc[py][px][o + 1][0], wv.y, v[dx + px].x);
                                ffma2(acc[py][px][o + 1][1], wv.y, v[dx + px].y);
                            }
                        }
                    } else {
                        #pragma unroll
                        for (int o = 0; o < OCG; o++) {
                            unsigned long long wv = swp[o];
                            #pragma unroll
                            for (int px = 0; px < 2; px++) {
                                ffma2(acc[py][px][o][0], wv, v[dx + px].x);
                                ffma2(acc[py][px][o][1], wv, v[dx + px].y);
                            }
                        }
                    }
                }
            }
        }
    }

    __syncthreads();
    #pragma unroll
    for (int py = 0; py < 2; py++)
        #pragma unroll
        for (int px = 0; px < 2; px++)
            #pragma unroll
            for (int o = 0; o < OCG; o++) {
                float* sap = sa + ((py * 2 + px) * OCG + o) * 260 + t;
                *(float2*)(sap    ) = *(float2*)&acc[py][px][o][0];
                *(float2*)(sap + 2) = *(float2*)&acc[py][px][o][1];
            }
    __syncthreads();

    if (tid < 4 * OCG) {
        float* row = sa + tid * 260;
        float r = 0.f;
        float4 nxt = *(float4*)row;
        for (int tt = 0; tt < TT; tt += 4) {
            float4 a = nxt;
            if (tt + 4 < TT) nxt = *(float4*)(row + tt + 4);
            float u[4] = {a.x, a.y, a.z, a.w};
            float o4[4];
            #pragma unroll
            for (int j = 0; j < 4; j++) {
                float v = u[j] + r - 10.0f;
                float s = (v >= 0.f) ? 1.f : 0.f;
                r = DREF * (r - 20.f * s);
                o4[j] = s;
            }
            *(float4*)(row + tt) = make_float4(o4[0], o4[1], o4[2], o4[3]);
        }
    }
    __syncthreads();

    if (tid < OCG) {
        const float* r0 = sa + (0 * OCG + tid) * 260;
        const float* r1 = sa + (1 * OCG + tid) * 260;
        const float* r2 = sa + (2 * OCG + tid) * 260;
        const float* r3 = sa + (3 * OCG + tid) * 260;
        float* ro = sa + tid * 260;
        float G1 = 0.f, G2 = 0.f, R = 0.f, h1 = 0.f, h2 = 0.f;
        for (int tt = 0; tt < TT; tt += 4) {
            float4 a = *(const float4*)(r0 + tt);
            float4 bb = *(const float4*)(r1 + tt);
            float4 c = *(const float4*)(r2 + tt);
            float4 d = *(const float4*)(r3 + tt);
            float pl[4] = {(a.x + bb.x) + (c.x + d.x), (a.y + bb.y) + (c.y + d.y),
                           (a.z + bb.z) + (c.z + d.z), (a.w + bb.w) + (c.w + d.w)};
            float o4[4];
            #pragma unroll
            for (int j = 0; j < 4; j++) {
                G1 = fmaf(DSR, G1, pl[j]);
                G2 = fmaf(DSR, G2, G1);
                float u = 2.75f * (PSC * (G2 - G1));
                float v = u + R - 10.0f;
                float s = (v >= 0.f) ? 1.f : 0.f;
                R = DREF * (R - 20.f * s);
                h1 = fmaf(DSR, h1, s);
                h2 = fmaf(DSR, h2, h1);
                o4[j] = PSC * (h2 - h1);
            }
            *(float4*)(ro + tt) = make_float4(o4[0], o4[1], o4[2], o4[3]);
        }
    }
    __syncthreads();

    #pragma unroll
    for (int o = 0; o < OCG; o++) {
        float* ob = out + (((long)b * OC + oc0 + o) * Ho + (ty + OP)) * (long)Wo * TT
                        + (long)(tx + OP) * TT + t;
        *(float4*)ob = *(const float4*)(sa + o * 260 + t);
    }
}

// ---------------------------------------------------------------------------
// Fused final stage: out = spike(conv1x1(psp(spike(up2(P7))))).
// One 64-thread block per output pixel (32x32). Phase A: 32 threads run the
// per-channel bilinear-gather + spike + psp recurrences (z_c -> smem).
// Phase B: 64 threads compute the channel dot with wo (ascending c, same fma
// order as the previous conv kernel). Phase C: thread 0 runs the final spike
// recurrence and stores. P8 never exists.
// ---------------------------------------------------------------------------
__global__ __launch_bounds__(64)
void upconv_kernel(const float* __restrict__ in /*P7 [4,32,16,16,256]*/,
                   const float* __restrict__ wo, float* __restrict__ out)
{
    __shared__ __align__(16) float sz[32][260];
    __shared__ __align__(16) float su[260];
    __shared__ float wsm[32];

    int tid = threadIdx.x;
    int pix = blockIdx.x;
    int x = pix & 31, y = (pix >> 5) & 31, b = pix >> 10;

    if (tid < 32) wsm[tid] = wo[tid];

    // Bilinear tap geometry (input 16x16), same as dyn MODE 3.
    int jy = y >> 1, jx = x >> 1;
    int ya, yb, xa, xb; float wya, wyb, wxa, wxb;
    if ((y & 1) == 0) { ya = (jy > 0) ? jy - 1 : 0; yb = jy; wya = 0.25f; wyb = 0.75f; }
    else              { ya = jy; yb = (jy + 1 < 16) ? jy + 1 : 15; wya = 0.75f; wyb = 0.25f; }
    if ((x & 1) == 0) { xa = (jx > 0) ? jx - 1 : 0; xb = jx; wxa = 0.25f; wxb = 0.75f; }
    else              { xa = jx; xb = (jx + 1 < 16) ? jx + 1 : 15; wxa = 0.75f; wxb = 0.25f; }
    float w00 = wya * wxa, w01 = wya * wxb, w10 = wyb * wxa, w11 = wyb * wxb;

    if (tid < 32) {
        int c = tid;
        const float* base = in + (long)(b * 32 + c) * 16 * 16 * TT;
        const float* p0 = base + ((long)ya * 16 + xa) * TT;
        const float* p1 = base + ((long)ya * 16 + xb) * TT;
        const float* p2 = base + ((long)yb * 16 + xa) * TT;
        const float* p3 = base + ((long)yb * 16 + xb) * TT;
        float g1 = 0.f, g2 = 0.f, r = 0.f;
        for (int tt = 0; tt < TT; tt += 4) {
            float4 a = *(const float4*)(p0 + tt);
            float4 bb = *(const float4*)(p1 + tt);
            float4 cc = *(const float4*)(p2 + tt);
            float4 d = *(const float4*)(p3 + tt);
            float u[4];
            u[0] = w00 * a.x + w01 * bb.x + w10 * cc.x + w11 * d.x;
            u[1] = w00 * a.y + w01 * bb.y + w10 * cc.y + w11 * d.y;
            u[2] = w00 * a.z + w01 * bb.z + w10 * cc.z + w11 * d.z;
            u[3] = w00 * a.w + w01 * bb.w + w10 * cc.w + w11 * d.w;
            float o4[4];
            #pragma unroll
            for (int j = 0; j < 4; j++) {
                float v = u[j] + r - 10.0f;
                float s = (v >= 0.f) ? 1.f : 0.f;
                r = DREF * (r - 20.f * s);
                g1 = fmaf(DSR, g1, s);
                g2 = fmaf(DSR, g2, g1);
                o4[j] = PSC * (g2 - g1);
            }
            *(float4*)&sz[c][tt] = make_float4(o4[0], o4[1], o4[2], o4[3]);
        }
    }
    __syncthreads();

    // Phase B: channel dot, t = tid*4 (64 threads x 4 timesteps = 256).
    {
        int t4 = tid * 4;
        float a0 = 0.f, a1 = 0.f, a2 = 0.f, a3 = 0.f;
        #pragma unroll 4
        for (int c = 0; c < 32; c++) {
            float w = wsm[c];
            float4 z = *(const float4*)&sz[c][t4];
            a0 = fmaf(w, z.x, a0);
            a1 = fmaf(w, z.y, a1);
            a2 = fmaf(w, z.z, a2);
            a3 = fmaf(w, z.w, a3);
        }
        *(float4*)&su[t4] = make_float4(a0, a1, a2, a3);
    }
    __syncthreads();

    // Phase C: final spike recurrence, direct store.
    if (tid == 0) {
        float* ob = out + ((long)b * 1024 + y * 32 + x) * TT;
        float r = 0.f;
        for (int tt = 0; tt < TT; tt += 4) {
            float4 a = *(const float4*)&su[tt];
            float u[4] = {a.x, a.y, a.z, a.w};
            float o4[4];
            #pragma unroll
            for (int j = 0; j < 4; j++) {
                float v = u[j] + r - 10.0f;
                float s = (v >= 0.f) ? 1.f : 0.f;
                r = DREF * (r - 20.f * s);
                o4[j] = s;
            }
            *(float4*)(ob + tt) = make_float4(o4[0], o4[1], o4[2], o4[3]);
        }
    }
}

// ---------------------------------------------------------------------------
// 7 launches.
// ---------------------------------------------------------------------------
extern "C" void kernel_launch(void* const* d_in, const int* in_sizes, int n_in,
                              void* d_out, int out_size)
{
    const float* inp = (const float*)d_in[0];
    const float* w1  = (const float*)d_in[1];
    const float* w2  = (const float*)d_in[2];
    const float* w3  = (const float*)d_in[3];
    const float* w4  = (const float*)d_in[4];
    const float* wo  = (const float*)d_in[5];
    float* out = (float*)d_out;

    float* WS;
    cudaGetSymbolAddress((void**)&WS, g_ws);
    float* P0 = WS + O_P0;  float* P2 = WS + O_P2;
    float* P4 = WS + O_P4;  float* P5 = WS + O_P5;
    float* P6 = WS + O_P6;  float* P7 = WS + O_P7;

    // P0 = psp(input), halo 2 for conv1
    dyn_kernel<0, 32, 32, 2><<<128, 32>>>(inp, P0, 4096);

    // P2 = pooled-fused conv1 -> 16x16, halo 1
    convpool_kernel<1, 5, 4, 32, 32, 16, 1><<<dim3(1024, 4), 64>>>(P0, w1, P2);

    // P4 = pooled-fused conv2 -> 8x8, halo 1
    convpool_kernel<16, 3, 4, 16, 16, 32, 1><<<dim3(256, 8), 64>>>(P2, w2, P4);

    // P5 = spike/psp(conv3(P4))   TW=2, PX=4, OCG=4
    conv_kernel<32, 3, 4, 4, 1, 8, 8, 64><<<dim3(64, 16), 128>>>(P4, w3, P5);

    // P6 = up+spike+psp(P5), halo 1   [4,64,16,16]
    dyn_kernel<3, 16, 16, 1><<<512, 128>>>(P5, P6, 65536);

    // P7 = spike/psp(conv4(P6))   TW=2, PX=4, OCG=8  (grid.y redundancy 8->4)
    conv_kernel<64, 3, 8, 4, 1, 16, 16, 32><<<dim3(256, 4), 128>>>(P6, w4, P7);

    // out = spike(conv1x1(psp(spike(up2(P7)))))  — P8 eliminated
    upconv_kernel<<<4096, 64>>>(P7, wo, out);
}

// round 16
// speedup vs baseline: 1.2403x; 1.2403x over previous
#include <cuda_runtime.h>

#define TT 256

// ---------------------------------------------------------------------------
// Workspace regions (zero-initialized device global; halos stay zero forever).
//  P0p [4,1,36,36,256]    P2p [4,16,18,18,256]   P4p [4,32,10,10,256]
//  P5  [4,64,8,8,256]     P6p [4,64,18,18,256]   P7 [4,32,16,16,256]
//  P8  [4,32,32,32,256]
// ---------------------------------------------------------------------------
#define O_P0 0L
#define O_P2 1327104L
#define O_P4 6635520L
#define O_P5 9912320L
#define O_P6 14106624L
#define O_P7 35340288L
#define O_P8 43728896L
#define WS_TOTAL 77283328L
__device__ float g_ws[WS_TOTAL];

__device__ __forceinline__ void ffma2(unsigned long long& acc,
                                      unsigned long long w,
                                      unsigned long long v) {
    asm("fma.rn.f32x2 %0, %1, %2, %0;" : "+l"(acc) : "l"(w), "l"(v));
}

#define DSR  0.9048374180359595f   // exp(-1/10)
#define PSC  0.27182818284590452f  // e/10
#define DREF 0.36787944117144233f  // exp(-1)

// ---------------------------------------------------------------------------
// Standalone dynamics kernel. MODE 0: psp only ; MODE 3: up2+spike+psp.
// ---------------------------------------------------------------------------
template<int MODE, int H, int W, int OPAD>
__global__ void dyn_kernel(const float* __restrict__ in, float* __restrict__ out,
                           int N)
{
    int n = blockIdx.x * blockDim.x + threadIdx.x;
    if (n >= N) return;

    constexpr int S  = (MODE == 3) ? 4 : 1;
    constexpr int CH = (S == 4) ? 8 : 16;
    constexpr int F4 = CH / 4;
    constexpr int NC = TT / CH;
    constexpr int Ho = H + 2 * OPAD;
    constexpr int Wo = W + 2 * OPAD;

    int x = n % W, y = (n / W) % H, bc = n / (W * H);

    const float* p[S];
    float w00 = 0.f, w01 = 0.f, w10 = 0.f, w11 = 0.f;

    if (MODE == 3) {
        constexpr int Hin = H / 2, Win = W / 2;
        int jy = y >> 1, jx = x >> 1;
        int ya, yb, xa, xb; float wya, wyb, wxa, wxb;
        if ((y & 1) == 0) { ya = (jy > 0) ? jy - 1 : 0; yb = jy; wya = 0.25f; wyb = 0.75f; }
        else              { ya = jy; yb = (jy + 1 < Hin) ? jy + 1 : Hin - 1; wya = 0.75f; wyb = 0.25f; }
        if ((x & 1) == 0) { xa = (jx > 0) ? jx - 1 : 0; xb = jx; wxa = 0.25f; wxb = 0.75f; }
        else              { xa = jx; xb = (jx + 1 < Win) ? jx + 1 : Win - 1; wxa = 0.75f; wxb = 0.25f; }
        const float* base = in + (long)bc * Hin * Win * TT;
        p[0] = base + ((long)ya * Win + xa) * TT; w00 = wya * wxa;
        p[1] = base + ((long)ya * Win + xb) * TT; w01 = wya * wxb;
        p[2] = base + ((long)yb * Win + xa) * TT; w10 = wyb * wxa;
        p[3] = base + ((long)yb * Win + xb) * TT; w11 = wyb * wxb;
    } else {
        p[0] = in + (long)n * TT;
    }

    float* ob = out + (((long)bc * Ho + (y + OPAD)) * Wo + (x + OPAD)) * TT;

    float g1 = 0.f, g2 = 0.f, r = 0.f;
    float4 A[S][F4], B[S][F4];

    auto load = [&](float4 (&buf)[S][F4], int c) {
        #pragma unroll
        for (int s = 0; s < S; s++)
            #pragma unroll
            for (int f = 0; f < F4; f++)
                buf[s][f] = *(const float4*)(p[s] + c * CH + f * 4);
    };

    auto compute = [&](float4 (&buf)[S][F4], int c) {
        #pragma unroll
        for (int f = 0; f < F4; f++) {
            float u[4];
            if (MODE == 3) {
                float4 a = buf[0][f], b = buf[1][f], cc = buf[2][f], d = buf[3][f];
                u[0] = w00 * a.x + w01 * b.x + w10 * cc.x + w11 * d.x;
                u[1] = w00 * a.y + w01 * b.y + w10 * cc.y + w11 * d.y;
                u[2] = w00 * a.z + w01 * b.z + w10 * cc.z + w11 * d.z;
                u[3] = w00 * a.w + w01 * b.w + w10 * cc.w + w11 * d.w;
            } else {
                float4 a = buf[0][f];
                u[0] = a.x; u[1] = a.y; u[2] = a.z; u[3] = a.w;
            }
            float o[4];
            #pragma unroll
            for (int j = 0; j < 4; j++) {
                if (MODE == 0) {
                    g1 = fmaf(DSR, g1, u[j]);
                    g2 = fmaf(DSR, g2, g1);
                    o[j] = PSC * (g2 - g1);
                } else {
                    float v = u[j] + r - 10.0f;
                    float s = (v >= 0.f) ? 1.f : 0.f;
                    r = DREF * (r - 20.f * s);
                    g1 = fmaf(DSR, g1, s);
                    g2 = fmaf(DSR, g2, g1);
                    o[j] = PSC * (g2 - g1);
                }
            }
            *(float4*)(ob + c * CH + f * 4) = make_float4(o[0], o[1], o[2], o[3]);
        }
    };

    load(A, 0);
    for (int c = 0; c < NC; c += 2) {
        load(B, c + 1);
        compute(A, c);
        if (c + 2 < NC) load(A, c + 2);
        compute(B, c + 1);
    }
}

// ---------------------------------------------------------------------------
// Fused conv + spike/psp epilogue (TW=4, 64-thread blocks — R13 version).
// PX x-adjacent pixels, OCG channels, zero-padded input, guard-free loads.
// EPI = 1: spike + psp.  EPI = 4: spike only (final layer).
// ---------------------------------------------------------------------------
template<int IC, int KS, int OCG, int PX, int EPI, int H, int W, int OC>
__global__ __launch_bounds__(64)
void conv_kernel(const float* __restrict__ in, const float* __restrict__ wgt,
                 float* __restrict__ out)
{
    constexpr int PAD  = KS / 2;
    constexpr int Hp   = H + 2 * PAD;
    constexpr int Wp   = W + 2 * PAD;
    constexpr int NCOL = KS + PX - 1;
    constexpr int WP   = W / PX;
    constexpr int SW_BYTES = IC * KS * KS * OCG * 8;
    constexpr int SA_BYTES = PX * OCG * 260 * 4;
    constexpr int SM_BYTES = SW_BYTES > SA_BYTES ? SW_BYTES : SA_BYTES;
    __shared__ __align__(16) unsigned char smem_raw[SM_BYTES];
    unsigned long long* sw = (unsigned long long*)smem_raw;
    float* sa = (float*)smem_raw;

    int tid = threadIdx.x;
    int t   = tid * 4;

    int pp = blockIdx.x;
    int x0 = (pp % WP) * PX;
    int y  = (pp / WP) % H;
    int b  = pp / (WP * H);
    int oc0 = blockIdx.y * OCG;

    for (int i = tid; i < IC * KS * KS * OCG; i += 64) {
        int o  = i % OCG;
        int rs = i / OCG;
        int ic = rs % IC;
        int kd = rs / IC;
        int kh = kd / KS, dx = kd % KS;
        unsigned u = __float_as_uint(
            wgt[((long)(oc0 + o) * IC + ic) * (KS * KS) + kh * KS + dx]);
        sw[i] = ((unsigned long long)u << 32) | u;
    }
    __syncthreads();

    unsigned long long acc[PX][OCG][2];
    #pragma unroll
    for (int p = 0; p < PX; p++)
        #pragma unroll
        for (int o = 0; o < OCG; o++) { acc[p][o][0] = 0ull; acc[p][o][1] = 0ull; }

    constexpr long planeTp = (long)Hp * Wp * TT;
    const float* inb = in + ((long)b * IC * Hp + y) * (long)Wp * TT + (long)x0 * TT + t;

    #pragma unroll
    for (int kh = 0; kh < KS; kh++) {
        const float* rp = inb + (long)kh * Wp * TT;
        #pragma unroll 2
        for (int ic = 0; ic < IC; ic++) {
            const float* icb = rp + (long)ic * planeTp;
            ulonglong2 v[NCOL];
            #pragma unroll
            for (int j = 0; j < NCOL; j++)
                v[j] = *(const ulonglong2*)(icb + j * TT);
            const unsigned long long* swp0 = sw + ((long)kh * KS * IC + ic) * OCG;
            #pragma unroll
            for (int dx = 0; dx < KS; dx++) {
                const unsigned long long* swp = swp0 + (long)dx * IC * OCG;
                if constexpr (OCG % 2 == 0) {
                    #pragma unroll
                    for (int o = 0; o < OCG; o += 2) {
                        ulonglong2 wv = *(const ulonglong2*)(swp + o);
                        #pragma unroll
                        for (int p = 0; p < PX; p++) {
                            ffma2(acc[p][o    ][0], wv.x, v[dx + p].x);
                            ffma2(acc[p][o    ][1], wv.x, v[dx + p].y);
                            ffma2(acc[p][o + 1][0], wv.y, v[dx + p].x);
                            ffma2(acc[p][o + 1][1], wv.y, v[dx + p].y);
                        }
                    }
                } else {
                    #pragma unroll
                    for (int o = 0; o < OCG; o++) {
                        unsigned long long wv = swp[o];
                        #pragma unroll
                        for (int p = 0; p < PX; p++) {
                            ffma2(acc[p][o][0], wv, v[dx + p].x);
                            ffma2(acc[p][o][1], wv, v[dx + p].y);
                        }
                    }
                }
            }
        }
    }

    __syncthreads();
    #pragma unroll
    for (int p = 0; p < PX; p++)
        #pragma unroll
        for (int o = 0; o < OCG; o++) {
            float* sap = sa + (p * OCG + o) * 260 + t;
            *(float2*)(sap    ) = *(float2*)&acc[p][o][0];
            *(float2*)(sap + 2) = *(float2*)&acc[p][o][1];
        }
    __syncthreads();

    if (tid < PX * OCG) {
        float* row = sa + tid * 260;
        float g1 = 0.f, g2 = 0.f, r = 0.f;
        float4 nxt = *(float4*)row;
        for (int tt = 0; tt < TT; tt += 4) {
            float4 a = nxt;
            if (tt + 4 < TT) nxt = *(float4*)(row + tt + 4);
            float u[4] = {a.x, a.y, a.z, a.w};
            float o4[4];
            #pragma unroll
            for (int j = 0; j < 4; j++) {
                float v = u[j] + r - 10.0f;
                float s = (v >= 0.f) ? 1.f : 0.f;
                r = DREF * (r - 20.f * s);
                if (EPI == 4) {
                    o4[j] = s;
                } else {
                    g1 = fmaf(DSR, g1, s);
                    g2 = fmaf(DSR, g2, g1);
                    o4[j] = PSC * (g2 - g1);
                }
            }
            *(float4*)(row + tt) = make_float4(o4[0], o4[1], o4[2], o4[3]);
        }
    }
    __syncthreads();

    constexpr long planeT = (long)H * W * TT;
    #pragma unroll
    for (int p = 0; p < PX; p++) {
        float* ob = out + ((long)b * OC + oc0) * planeT + ((long)y * W + x0 + p) * TT + t;
        #pragma unroll
        for (int o = 0; o < OCG; o++)
            *(float4*)(ob + o * planeT) = *(const float4*)(sa + (p * OCG + o) * 260 + t);
    }
}

// ---------------------------------------------------------------------------
// Conv + FUSED POOL epilogue (pool/psp commutation). Unchanged from R13.
// ---------------------------------------------------------------------------
template<int IC, int KS, int OCG, int H, int W, int OC, int OP>
__global__ __launch_bounds__(64)
void convpool_kernel(const float* __restrict__ in, const float* __restrict__ wgt,
                     float* __restrict__ out)
{
    constexpr int PAD  = KS / 2;
    constexpr int Hp   = H + 2 * PAD;
    constexpr int Wp   = W + 2 * PAD;
    constexpr int NCOL = KS + 1;
    constexpr int NROW = KS + 1;
    constexpr int H2   = H / 2, W2 = W / 2;
    constexpr int Ho   = H2 + 2 * OP, Wo = W2 + 2 * OP;
    constexpr int SW_BYTES = IC * KS * KS * OCG * 8;
    constexpr int SA_BYTES = 4 * OCG * 260 * 4;
    constexpr int SM_BYTES = SW_BYTES > SA_BYTES ? SW_BYTES : SA_BYTES;
    __shared__ __align__(16) unsigned char smem_raw[SM_BYTES];
    unsigned long long* sw = (unsigned long long*)smem_raw;
    float* sa = (float*)smem_raw;

    int tid = threadIdx.x;
    int t   = tid * 4;

    int pp = blockIdx.x;
    int tx = pp % W2;
    int ty = (pp / W2) % H2;
    int b  = pp / (W2 * H2);
    int x0 = tx * 2, y0 = ty * 2;
    int oc0 = blockIdx.y * OCG;

    for (int i = tid; i < IC * KS * KS * OCG; i += 64) {
        int o  = i % OCG;
        int rs = i / OCG;
        int ic = rs % IC;
        int kd = rs / IC;
        int kh = kd / KS, dx = kd % KS;
        unsigned u = __float_as_uint(
            wgt[((long)(oc0 + o) * IC + ic) * (KS * KS) + kh * KS + dx]);
        sw[i] = ((unsigned long long)u << 32) | u;
    }
    __syncthreads();

    unsigned long long acc[2][2][OCG][2];
    #pragma unroll
    for (int py = 0; py < 2; py++)
        #pragma unroll
        for (int px = 0; px < 2; px++)
            #pragma unroll
            for (int o = 0; o < OCG; o++) { acc[py][px][o][0] = 0ull; acc[py][px][o][1] = 0ull; }

    constexpr long planeTp = (long)Hp * Wp * TT;
    const float* inb = in + ((long)b * IC * Hp + y0) * (long)Wp * TT + (long)x0 * TT + t;

    #pragma unroll
    for (int rr = 0; rr < NROW; rr++) {
        const float* rp = inb + (long)rr * Wp * TT;
        #pragma unroll 2
        for (int ic = 0; ic < IC; ic++) {
            const float* icb = rp + (long)ic * planeTp;
            ulonglong2 v[NCOL];
            #pragma unroll
            for (int j = 0; j < NCOL; j++)
                v[j] = *(const ulonglong2*)(icb + j * TT);
            #pragma unroll
            for (int py = 0; py < 2; py++) {
                int kh = rr - py;
                if (kh < 0 || kh >= KS) continue;
                const unsigned long long* swp0 = sw + ((long)kh * KS * IC + ic) * OCG;
                #pragma unroll
                for (int dx = 0; dx < KS; dx++) {
                    const unsigned long long* swp = swp0 + (long)dx * IC * OCG;
                    if constexpr (OCG % 2 == 0) {
                        #pragma unroll
                        for (int o = 0; o < OCG; o += 2) {
                            ulonglong2 wv = *(const ulonglong2*)(swp + o);
                            #pragma unroll
                            for (int px = 0; px < 2; px++) {
                                ffma2(acc[py][px][o    ][0], wv.x, v[dx + px].x);
                                ffma2(acc[py][px][o    ][1], wv.x, v[dx + px].y);
                                ffma2(acc[py][px][o + 1][0], wv.y, v[dx + px].x);
                                ffma2(acc[py][px][o + 1][1], wv.y, v[dx + px].y);
                            }
                        }
                    } else {
                        #pragma unroll
                        for (int o = 0; o < OCG; o++) {
                            unsigned long long wv = swp[o];
                            #pragma unroll
                            for (int px = 0; px < 2; px++) {
                                ffma2(acc[py][px][o][0], wv, v[dx + px].x);
                                ffma2(acc[py][px][o][1], wv, v[dx + px].y);
                            }
                        }
                    }
                }
            }
        }
    }

    __syncthreads();
    #pragma unroll
    for (int py = 0; py < 2; py++)
        #pragma unroll
        for (int px = 0; px < 2; px++)
            #pragma unroll
            for (int o = 0; o < OCG; o++) {
                float* sap = sa + ((py * 2 + px) * OCG + o) * 260 + t;
                *(float2*)(sap    ) = *(float2*)&acc[py][px][o][0];
                *(float2*)(sap + 2) = *(float2*)&acc[py][px][o][1];
            }
    __syncthreads();

    if (tid < 4 * OCG) {
        float* row = sa + tid * 260;
        float r = 0.f;
        float4 nxt = *(float4*)row;
        for (int tt = 0; tt < TT; tt += 4) {
            float4 a = nxt;
            if (tt + 4 < TT) nxt = *(float4*)(row + tt + 4);
            float u[4] = {a.x, a.y, a.z, a.w};
            float o4[4];
            #pragma unroll
            for (int j = 0; j < 4; j++) {
                float v = u[j] + r - 10.0f;
                float s = (v >= 0.f) ? 1.f : 0.f;
                r = DREF * (r - 20.f * s);
                o4[j] = s;
            }
            *(float4*)(row + tt) = make_float4(o4[0], o4[1], o4[2], o4[3]);
        }
    }
    __syncthreads();

    if (tid < OCG) {
        const float* r0 = sa + (0 * OCG + tid) * 260;
        const float* r1 = sa + (1 * OCG + tid) * 260;
        const float* r2 = sa + (2 * OCG + tid) * 260;
        const float* r3 = sa + (3 * OCG + tid) * 260;
        float* ro = sa + tid * 260;
        float G1 = 0.f, G2 = 0.f, R = 0.f, h1 = 0.f, h2 = 0.f;
        for (int tt = 0; tt < TT; tt += 4) {
            float4 a = *(const float4*)(r0 + tt);
            float4 bb = *(const float4*)(r1 + tt);
            float4 c = *(const float4*)(r2 + tt);
            float4 d = *(const float4*)(r3 + tt);
            float pl[4] = {(a.x + bb.x) + (c.x + d.x), (a.y + bb.y) + (c.y + d.y),
                           (a.z + bb.z) + (c.z + d.z), (a.w + bb.w) + (c.w + d.w)};
            float o4[4];
            #pragma unroll
            for (int j = 0; j < 4; j++) {
                G1 = fmaf(DSR, G1, pl[j]);
                G2 = fmaf(DSR, G2, G1);
                float u = 2.75f * (PSC * (G2 - G1));
                float v = u + R - 10.0f;
                float s = (v >= 0.f) ? 1.f : 0.f;
                R = DREF * (R - 20.f * s);
                h1 = fmaf(DSR, h1, s);
                h2 = fmaf(DSR, h2, h1);
                o4[j] = PSC * (h2 - h1);
            }
            *(float4*)(ro + tt) = make_float4(o4[0], o4[1], o4[2], o4[3]);
        }
    }
    __syncthreads();

    #pragma unroll
    for (int o = 0; o < OCG; o++) {
        float* ob = out + (((long)b * OC + oc0 + o) * Ho + (ty + OP)) * (long)Wo * TT
                        + (long)(tx + OP) * TT + t;
        *(float4*)ob = *(const float4*)(sa + o * 260 + t);
    }
}

// ---------------------------------------------------------------------------
// 8 launches (R13 schedule; ONLY conv4's tile shape changed: PX 2 -> 4).
// ---------------------------------------------------------------------------
extern "C" void kernel_launch(void* const* d_in, const int* in_sizes, int n_in,
                              void* d_out, int out_size)
{
    const float* inp = (const float*)d_in[0];
    const float* w1  = (const float*)d_in[1];
    const float* w2  = (const float*)d_in[2];
    const float* w3  = (const float*)d_in[3];
    const float* w4  = (const float*)d_in[4];
    const float* wo  = (const float*)d_in[5];
    float* out = (float*)d_out;

    float* WS;
    cudaGetSymbolAddress((void**)&WS, g_ws);
    float* P0 = WS + O_P0;  float* P2 = WS + O_P2;
    float* P4 = WS + O_P4;  float* P5 = WS + O_P5;
    float* P6 = WS + O_P6;  float* P7 = WS + O_P7;
    float* P8 = WS + O_P8;

    // P0 = psp(input), halo 2 for conv1
    dyn_kernel<0, 32, 32, 2><<<128, 32>>>(inp, P0, 4096);

    // P2 = pooled-fused conv1 -> 16x16, halo 1
    convpool_kernel<1, 5, 4, 32, 32, 16, 1><<<dim3(1024, 4), 64>>>(P0, w1, P2);

    // P4 = pooled-fused conv2 -> 8x8, halo 1
    convpool_kernel<16, 3, 4, 16, 16, 32, 1><<<dim3(256, 8), 64>>>(P2, w2, P4);

    // P5 = spike/psp(conv3(P4))   PX=4, OCG=4   [4,64,8,8,256]
    conv_kernel<32, 3, 4, 4, 1, 8, 8, 64><<<dim3(64, 16), 64>>>(P4, w3, P5);

    // P6 = up+spike+psp(P5), halo 1   [4,64,16,16]
    dyn_kernel<3, 16, 16, 1><<<512, 128>>>(P5, P6, 65536);

    // P7 = spike/psp(conv4(P6))   PX=4, OCG=4   (the single change vs R13)
    conv_kernel<64, 3, 4, 4, 1, 16, 16, 32><<<dim3(256, 8), 64>>>(P6, w4, P7);

    // P8 = up+spike+psp(P7), unpadded   [4,32,32,32]
    dyn_kernel<3, 32, 32, 0><<<1024, 128>>>(P7, P8, 131072);

    // out = spike(conv_out(P8))   PX=2, OCG=1
    conv_kernel<32, 1, 1, 2, 4, 32, 32, 1><<<dim3(2048, 1), 64>>>(P8, wo, out);
}

// round 17
// speedup vs baseline: 1.2921x; 1.0417x over previous
#include <cuda_runtime.h>

#define TT 256

// ---------------------------------------------------------------------------
// Workspace: dedicated zero-initialized regions; padded halos stay zero.
// ---------------------------------------------------------------------------
#define O_P0 0L
#define O_P1 1327104L
#define O_P2 18104320L
#define O_P3 23412736L
#define O_P4 31801344L
#define O_P5 35078144L
#define O_P6 39272448L
#define O_P7 60506112L
#define O_P8 68894720L
#define WS_TOTAL 102449152L
__device__ float g_ws[WS_TOTAL];

__device__ __forceinline__ void ffma2(unsigned long long& acc,
                                      unsigned long long w,
                                      unsigned long long v) {
    asm("fma.rn.f32x2 %0, %1, %2, %0;" : "+l"(acc) : "l"(w), "l"(v));
}

#define DSR  0.9048374180359595f   // exp(-1/10)
#define PSC  0.27182818284590452f  // e/10
#define DREF 0.36787944117144233f  // exp(-1)

// ---------------------------------------------------------------------------
// Standalone dynamics kernel (input-psp, pool, upsample layers).
// MODE 0: psp ; MODE 2: pool+spike+psp ; MODE 3: up2+spike+psp
// ---------------------------------------------------------------------------
template<int MODE, int H, int W, int OPAD>
__global__ void dyn_kernel(const float* __restrict__ in, float* __restrict__ out,
                           int N)
{
    int n = blockIdx.x * blockDim.x + threadIdx.x;
    if (n >= N) return;

    constexpr int S  = (MODE == 2 || MODE == 3) ? 4 : 1;
    constexpr int CH = (S == 4) ? 8 : 16;
    constexpr int F4 = CH / 4;
    constexpr int NC = TT / CH;
    constexpr int Ho = H + 2 * OPAD;
    constexpr int Wo = W + 2 * OPAD;

    int x = n % W, y = (n / W) % H, bc = n / (W * H);

    const float* p[S];
    float w00 = 0.f, w01 = 0.f, w10 = 0.f, w11 = 0.f;

    if (MODE == 2) {
        constexpr int Win = 2 * W;
        const float* base = in + (((long)bc * (2 * H) + 2 * y) * Win + 2 * x) * TT;
        p[0] = base;
        p[1] = base + TT;
        p[2] = base + (long)Win * TT;
        p[3] = base + (long)(Win + 1) * TT;
    } else if (MODE == 3) {
        constexpr int Hin = H / 2, Win = W / 2;
        int jy = y >> 1, jx = x >> 1;
        int ya, yb, xa, xb; float wya, wyb, wxa, wxb;
        if ((y & 1) == 0) { ya = (jy > 0) ? jy - 1 : 0; yb = jy; wya = 0.25f; wyb = 0.75f; }
        else              { ya = jy; yb = (jy + 1 < Hin) ? jy + 1 : Hin - 1; wya = 0.75f; wyb = 0.25f; }
        if ((x & 1) == 0) { xa = (jx > 0) ? jx - 1 : 0; xb = jx; wxa = 0.25f; wxb = 0.75f; }
        else              { xa = jx; xb = (jx + 1 < Win) ? jx + 1 : Win - 1; wxa = 0.75f; wxb = 0.25f; }
        const float* base = in + (long)bc * Hin * Win * TT;
        p[0] = base + ((long)ya * Win + xa) * TT; w00 = wya * wxa;
        p[1] = base + ((long)ya * Win + xb) * TT; w01 = wya * wxb;
        p[2] = base + ((long)yb * Win + xa) * TT; w10 = wyb * wxa;
        p[3] = base + ((long)yb * Win + xb) * TT; w11 = wyb * wxb;
    } else {
        p[0] = in + (long)n * TT;
    }

    float* ob = out + (((long)bc * Ho + (y + OPAD)) * Wo + (x + OPAD)) * TT;

    float g1 = 0.f, g2 = 0.f, r = 0.f;
    float4 A[S][F4], B[S][F4];

    auto load = [&](float4 (&buf)[S][F4], int c) {
        #pragma unroll
        for (int s = 0; s < S; s++)
            #pragma unroll
            for (int f = 0; f < F4; f++)
                buf[s][f] = *(const float4*)(p[s] + c * CH + f * 4);
    };

    auto compute = [&](float4 (&buf)[S][F4], int c) {
        #pragma unroll
        for (int f = 0; f < F4; f++) {
            float u[4];
            if (MODE == 2) {
                float4 a = buf[0][f], b = buf[1][f], cc = buf[2][f], d = buf[3][f];
                u[0] = 2.75f * ((a.x + b.x) + (cc.x + d.x));
                u[1] = 2.75f * ((a.y + b.y) + (cc.y + d.y));
                u[2] = 2.75f * ((a.z + b.z) + (cc.z + d.z));
                u[3] = 2.75f * ((a.w + b.w) + (cc.w + d.w));
            } else if (MODE == 3) {
                float4 a = buf[0][f], b = buf[1][f], cc = buf[2][f], d = buf[3][f];
                u[0] = w00 * a.x + w01 * b.x + w10 * cc.x + w11 * d.x;
                u[1] = w00 * a.y + w01 * b.y + w10 * cc.y + w11 * d.y;
                u[2] = w00 * a.z + w01 * b.z + w10 * cc.z + w11 * d.z;
                u[3] = w00 * a.w + w01 * b.w + w10 * cc.w + w11 * d.w;
            } else {
                float4 a = buf[0][f];
                u[0] = a.x; u[1] = a.y; u[2] = a.z; u[3] = a.w;
            }
            float o[4];
            #pragma unroll
            for (int j = 0; j < 4; j++) {
                if (MODE == 0) {
                    g1 = fmaf(DSR, g1, u[j]);
                    g2 = fmaf(DSR, g2, g1);
                    o[j] = PSC * (g2 - g1);
                } else {
                    float v = u[j] + r - 10.0f;
                    float s = (v >= 0.f) ? 1.f : 0.f;
                    r = DREF * (r - 20.f * s);
                    g1 = fmaf(DSR, g1, s);
                    g2 = fmaf(DSR, g2, g1);
                    o[j] = PSC * (g2 - g1);
                }
            }
            *(float4*)(ob + c * CH + f * 4) = make_float4(o[0], o[1], o[2], o[3]);
        }
    };

    load(A, 0);
    for (int c = 0; c < NC; c += 2) {
        load(B, c + 1);
        compute(A, c);
        if (c + 2 < NC) load(A, c + 2);
        compute(B, c + 1);
    }
}

// ---------------------------------------------------------------------------
// Fused conv + spike/psp epilogue. 64 threads, TW=4, PX pixels, OCG channels.
// OCG=8: per (kh,ic): NCOL LDG.128 (16 wf) + 12 broadcast-LDS (12 wf) feed
// 96 FFMA2 (48 SM-cyc) -> FMA-bound instead of L1-wavefront-bound.
// Zero-padded input, guard-free. EPI=1: spike+psp. EPI=4: spike only.
// ---------------------------------------------------------------------------
template<int IC, int KS, int OCG, int PX, int EPI, int H, int W, int OC>
__global__ __launch_bounds__(64)
void conv_kernel(const float* __restrict__ in, const float* __restrict__ wgt,
                 float* __restrict__ out)
{
    constexpr int PAD  = KS / 2;
    constexpr int Hp   = H + 2 * PAD;
    constexpr int Wp   = W + 2 * PAD;
    constexpr int NCOL = KS + PX - 1;
    constexpr int WP   = W / PX;
    constexpr int SW_BYTES = IC * KS * KS * OCG * 8;
    constexpr int SA_BYTES = PX * OCG * 260 * 4;
    constexpr int SM_BYTES = SW_BYTES > SA_BYTES ? SW_BYTES : SA_BYTES;
    __shared__ __align__(16) unsigned char smem_raw[SM_BYTES];
    unsigned long long* sw = (unsigned long long*)smem_raw;
    float* sa = (float*)smem_raw;

    int tid = threadIdx.x;
    int t   = tid * 4;

    int pp = blockIdx.x;
    int x0 = (pp % WP) * PX;
    int y  = (pp / WP) % H;
    int b  = pp / (WP * H);
    int oc0 = blockIdx.y * OCG;

    // Weight table in [kh][dx][ic][oc] order, f32 duplicated into u64 halves.
    for (int i = tid; i < IC * KS * KS * OCG; i += 64) {
        int o  = i % OCG;
        int rs = i / OCG;
        int ic = rs % IC;
        int kd = rs / IC;
        int kh = kd / KS, dx = kd % KS;
        unsigned u = __float_as_uint(
            wgt[((long)(oc0 + o) * IC + ic) * (KS * KS) + kh * KS + dx]);
        sw[i] = ((unsigned long long)u << 32) | u;
    }
    __syncthreads();

    unsigned long long acc[PX][OCG][2];
    #pragma unroll
    for (int p = 0; p < PX; p++)
        #pragma unroll
        for (int o = 0; o < OCG; o++) { acc[p][o][0] = 0ull; acc[p][o][1] = 0ull; }

    constexpr long planeTp = (long)Hp * Wp * TT;
    const float* inb = in + ((long)b * IC * Hp + y) * (long)Wp * TT + (long)x0 * TT + t;

    #pragma unroll
    for (int kh = 0; kh < KS; kh++) {
        const float* rp = inb + (long)kh * Wp * TT;
        #pragma unroll 2
        for (int ic = 0; ic < IC; ic++) {
            const float* icb = rp + (long)ic * planeTp;
            ulonglong2 v[NCOL];
            #pragma unroll
            for (int j = 0; j < NCOL; j++)
                v[j] = *(const ulonglong2*)(icb + j * TT);
            const unsigned long long* swp0 = sw + ((long)kh * KS * IC + ic) * OCG;
            #pragma unroll
            for (int dx = 0; dx < KS; dx++) {
                const unsigned long long* swp = swp0 + (long)dx * IC * OCG;
                if constexpr (OCG % 2 == 0) {
                    #pragma unroll
                    for (int o = 0; o < OCG; o += 2) {
                        ulonglong2 wv = *(const ulonglong2*)(swp + o);
                        #pragma unroll
                        for (int p = 0; p < PX; p++) {
                            ffma2(acc[p][o    ][0], wv.x, v[dx + p].x);
                            ffma2(acc[p][o    ][1], wv.x, v[dx + p].y);
                            ffma2(acc[p][o + 1][0], wv.y, v[dx + p].x);
                            ffma2(acc[p][o + 1][1], wv.y, v[dx + p].y);
                        }
                    }
                } else {
                    #pragma unroll
                    for (int o = 0; o < OCG; o++) {
                        unsigned long long wv = swp[o];
                        #pragma unroll
                        for (int p = 0; p < PX; p++) {
                            ffma2(acc[p][o][0], wv, v[dx + p].x);
                            ffma2(acc[p][o][1], wv, v[dx + p].y);
                        }
                    }
                }
            }
        }
    }

    __syncthreads();
    #pragma unroll
    for (int p = 0; p < PX; p++)
        #pragma unroll
        for (int o = 0; o < OCG; o++) {
            float* sap = sa + (p * OCG + o) * 260 + t;
            *(float2*)(sap    ) = *(float2*)&acc[p][o][0];
            *(float2*)(sap + 2) = *(float2*)&acc[p][o][1];
        }
    __syncthreads();

    if (tid < PX * OCG) {
        float* row = sa + tid * 260;
        float g1 = 0.f, g2 = 0.f, r = 0.f;
        float4 nxt = *(float4*)row;
        for (int tt = 0; tt < TT; tt += 4) {
            float4 a = nxt;
            if (tt + 4 < TT) nxt = *(float4*)(row + tt + 4);
            float u[4] = {a.x, a.y, a.z, a.w};
            float o4[4];
            #pragma unroll
            for (int j = 0; j < 4; j++) {
                float v = u[j] + r - 10.0f;
                float s = (v >= 0.f) ? 1.f : 0.f;
                r = DREF * (r - 20.f * s);
                if (EPI == 4) {
                    o4[j] = s;
                } else {
                    g1 = fmaf(DSR, g1, s);
                    g2 = fmaf(DSR, g2, g1);
                    o4[j] = PSC * (g2 - g1);
                }
            }
            *(float4*)(row + tt) = make_float4(o4[0], o4[1], o4[2], o4[3]);
        }
    }
    __syncthreads();

    constexpr long planeT = (long)H * W * TT;
    #pragma unroll
    for (int p = 0; p < PX; p++) {
        float* ob = out + ((long)b * OC + oc0) * planeT + ((long)y * W + x0 + p) * TT + t;
        #pragma unroll
        for (int o = 0; o < OCG; o++)
            *(float4*)(ob + o * planeT) = *(const float4*)(sa + (p * OCG + o) * 260 + t);
    }
}

// ---------------------------------------------------------------------------
// 10 launches (R11 schedule; conv2/3/4 OCG 4 -> 8 is the only change).
// ---------------------------------------------------------------------------
extern "C" void kernel_launch(void* const* d_in, const int* in_sizes, int n_in,
                              void* d_out, int out_size)
{
    const float* inp = (const float*)d_in[0];
    const float* w1  = (const float*)d_in[1];
    const float* w2  = (const float*)d_in[2];
    const float* w3  = (const float*)d_in[3];
    const float* w4  = (const float*)d_in[4];
    const float* wo  = (const float*)d_in[5];
    float* out = (float*)d_out;

    float* WS;
    cudaGetSymbolAddress((void**)&WS, g_ws);
    float* P0 = WS + O_P0;  float* P1 = WS + O_P1;
    float* P2 = WS + O_P2;  float* P3 = WS + O_P3;
    float* P4 = WS + O_P4;  float* P5 = WS + O_P5;
    float* P6 = WS + O_P6;  float* P7 = WS + O_P7;
    float* P8 = WS + O_P8;

    // P0 = psp(input), halo 2 for conv1
    dyn_kernel<0, 32, 32, 2><<<128, 32>>>(inp, P0, 4096);

    // P1 = spike/psp(conv1(P0))        IC=1,  OCG=8, PX=2
    conv_kernel<1, 5, 8, 2, 1, 32, 32, 16><<<dim3(2048, 2), 64>>>(P0, w1, P1);

    // P2 = pool+spike+psp(P1), halo 1   [4,16,16,16]
    dyn_kernel<2, 16, 16, 1><<<256, 64>>>(P1, P2, 16384);

    // P3 = spike/psp(conv2(P2))        IC=16, OCG=8, PX=2
    conv_kernel<16, 3, 8, 2, 1, 16, 16, 32><<<dim3(512, 4), 64>>>(P2, w2, P3);

    // P4 = pool+spike+psp(P3), halo 1   [4,32,8,8]
    dyn_kernel<2, 8, 8, 1><<<256, 32>>>(P3, P4, 8192);

    // P5 = spike/psp(conv3(P4))        IC=32, OCG=8, PX=2
    conv_kernel<32, 3, 8, 2, 1, 8, 8, 64><<<dim3(128, 8), 64>>>(P4, w3, P5);

    // P6 = up+spike+psp(P5), halo 1   [4,64,16,16]
    dyn_kernel<3, 16, 16, 1><<<512, 128>>>(P5, P6, 65536);

    // P7 = spike/psp(conv4(P6))        IC=64, OCG=8, PX=2
    conv_kernel<64, 3, 8, 2, 1, 16, 16, 32><<<dim3(512, 4), 64>>>(P6, w4, P7);

    // P8 = up+spike+psp(P7), unpadded   [4,32,32,32]
    dyn_kernel<3, 32, 32, 0><<<1024, 128>>>(P7, P8, 131072);

    // out = spike(conv_out(P8))        IC=32, OCG=1, PX=2
    conv_kernel<32, 1, 1, 2, 4, 32, 32, 1><<<dim3(2048, 1), 64>>>(P8, wo, out);
}